// round 9
// baseline (speedup 1.0000x reference)
#include <cuda_runtime.h>
#include <cuda_fp16.h>
#include <cstdint>
#include <cstring>
#include <algorithm>

// ===================== Problem constants (static graph) =====================
#define VOCAB    512
#define T_LEN    64
#define D_MODEL  32
#define N_NODES  4000
#define N_LAYERS 5
#define N_BIAS   2
#define BATCH    512
#define N_IN     (T_LEN * D_MODEL)          // 2048
#define N_SRC0   (N_IN + N_BIAS)            // 2050 : first dst node id
#define N_DST    (N_NODES - N_SRC0)         // 1950 : hidden + vocab dst nodes
#define MAX_EDGES 262144                    // expected ~166.8k
#define NLAY     (N_LAYERS + 1)             // 6 sparse layers

#define NSEG 8                               // edge segments per work item
#define TPB  (32 * NSEG)                     // 256 threads
#define GRID 592                             // 4 blocks/SM x 148 SMs: all resident

// ===================== Device globals (no allocation allowed) ===============
__device__ float2 g_packed[MAX_EDGES];                    // {weight, __int_as_float(src*BATCH)}
__device__ int    g_rowptr[N_DST + 2];                    // CSR over local dst index
__device__ __align__(128) __half g_vals[N_NODES * BATCH]; // fp16 activation slab (4.1 MB)
__device__ int    g_bar[8];                               // monotonic barrier counters

// ===================== Host-side: numpy-exact MT19937 =======================
struct MT19937 {
    uint32_t mt[624];
    int idx;
    void seed(uint32_t s) {
        mt[0] = s;
        for (int i = 1; i < 624; i++)
            mt[i] = 1812433253u * (mt[i - 1] ^ (mt[i - 1] >> 30)) + (uint32_t)i;
        idx = 624;
    }
    inline uint32_t next() {
        if (idx >= 624) {
            for (int i = 0; i < 624; i++) {
                uint32_t y = (mt[i] & 0x80000000u) | (mt[(i + 1) % 624] & 0x7fffffffu);
                mt[i] = mt[(i + 397) % 624] ^ (y >> 1);
                if (y & 1u) mt[i] ^= 0x9908b0dfu;
            }
            idx = 0;
        }
        uint32_t y = mt[idx++];
        y ^= y >> 11;
        y ^= (y << 7)  & 0x9d2c5680u;
        y ^= (y << 15) & 0xefc60000u;
        y ^= y >> 18;
        return y;
    }
    inline double rdouble() {  // numpy legacy rk_double
        uint32_t a = next() >> 5, b = next() >> 6;
        return ((double)a * 67108864.0 + (double)b) / 9007199254740992.0;
    }
    inline uint64_t next64() {  // numpy mt19937_next64: hi then lo
        uint64_t hi = next();
        uint64_t lo = next();
        return (hi << 32) | lo;
    }
};

// ===================== Host graph build (exact numpy replica) ===============
struct Params {
    int node_base[NLAY];
    int row_base[NLAY];
    int size[NLAY];
    int nedges;
};

static uint32_t h_emeta[MAX_EDGES];   // (widx << 12) | src : GPU reads via ATS
static int      h_rowptr[N_DST + 2];
static Params   h_params;

static void build_graph_host() {
    MT19937 mt;
    mt.seed(0u);

    int sizes[NLAY];
    {
        int nh = N_NODES - N_SRC0 - VOCAB;  // 1438
        for (int i = 0; i < N_LAYERS; i++)
            sizes[i] = nh / N_LAYERS + (i < nh % N_LAYERS ? 1 : 0);
        sizes[N_LAYERS] = VOCAB;
    }

    static int esrc[MAX_EDGES];
    static int edst[MAX_EDGES];

    int start = N_SRC0;
    int row_base = 0;
    int eidx = 0;

    for (int l = 0; l < NLAY; l++) {
        int size = sizes[l];
        int lbase = eidx;
        int colcnt[VOCAB];
        for (int v = 0; v < size; v++) colcnt[v] = 0;

        for (int u = 0; u < start; u++) {
            for (int v = 0; v < size; v++) {
                double x = mt.rdouble();
                if (x < 0.03) {
                    esrc[eidx] = u;
                    edst[eidx] = v;
                    colcnt[v]++;
                    eidx++;
                }
            }
        }

        // empty-column fix (probability ~1e-24; exact replica anyway)
        int emptyCols[VOCAB], nEmpty = 0;
        for (int v = 0; v < size; v++) if (colcnt[v] == 0) emptyCols[nEmpty++] = v;
        if (nEmpty) {
            uint64_t rng = (uint64_t)(start - 1);
            uint64_t mask = rng;
            mask |= mask >> 1; mask |= mask >> 2; mask |= mask >> 4;
            mask |= mask >> 8; mask |= mask >> 16; mask |= mask >> 32;
            for (int k = 0; k < nEmpty; k++) {
                uint64_t val;
                do { val = mt.next64() & mask; } while (val > rng);
                esrc[eidx] = (int)val;
                edst[eidx] = emptyCols[k];
                colcnt[emptyCols[k]]++;
                eidx++;
            }
            struct P { int s, d; };
            static P tmp[MAX_EDGES];
            int n = eidx - lbase;
            for (int i = 0; i < n; i++) tmp[i] = {esrc[lbase + i], edst[lbase + i]};
            std::sort(tmp, tmp + n, [](const P& a, const P& b) {
                return a.s != b.s ? a.s < b.s : a.d < b.d;
            });
            for (int i = 0; i < n; i++) { esrc[lbase + i] = tmp[i].s; edst[lbase + i] = tmp[i].d; }
        }

        // dst-sorted CSR; weight index = src-major position (== e)
        int colstart[VOCAB + 1];
        colstart[0] = lbase;
        for (int v = 0; v < size; v++) colstart[v + 1] = colstart[v] + colcnt[v];
        for (int v = 0; v < size; v++) h_rowptr[row_base + v] = colstart[v];
        int fill[VOCAB];
        for (int v = 0; v < size; v++) fill[v] = colstart[v];
        for (int e = lbase; e < eidx; e++) {
            int v = edst[e];
            h_emeta[fill[v]] = ((uint32_t)e << 12) | (uint32_t)esrc[e];
            fill[v]++;
        }

        h_params.node_base[l] = start;
        h_params.row_base[l]  = row_base;
        h_params.size[l]      = size;
        row_base += size;
        start    += size;
    }
    h_rowptr[N_DST] = eidx;
    h_params.nedges = eidx;
}

// ===================== Device: grid barrier ================================
// Monotonic-counter barrier: replay-safe (no reset needed). Ticket t waits
// until the counter reaches (t/GRID + 1)*GRID. Writer side: threadfence
// before arrive (release); reader side: fence after spin (acquire-ish).
__device__ __forceinline__ void grid_barrier(int b) {
    __syncthreads();
    if (threadIdx.x == 0) {
        __threadfence();
        int ticket = atomicAdd(&g_bar[b], 1);
        int target = (ticket / GRID + 1) * GRID;
        while (*(volatile int*)&g_bar[b] < target) {}
        __threadfence();
    }
    __syncthreads();
}

// ===================== The single persistent kernel =========================
// Phase 0: pull graph meta from HOST memory (Grace ATS), gather weights into
//          packed records; write embed values (fp16) for input+bias nodes.
// Barrier. Then 6 sparse layers, each a strided loop over work items
// (dst row x 128-col group); NSEG=8 segment-warps reduce through smem.
__global__ void __launch_bounds__(TPB, 6)
rwnn_kernel(Params p,
            const uint32_t* __restrict__ hostE,
            const int*      __restrict__ hostR,
            const int*      __restrict__ ids,
            const float*    __restrict__ tok,
            const float*    __restrict__ pos,
            const float*    __restrict__ weights,
            float*          __restrict__ out) {
    __shared__ float4 red[NSEG][32];

    int tid  = threadIdx.x;
    int lane = tid & 31;
    int seg  = tid >> 5;
    int gtid = blockIdx.x * TPB + tid;
    const int GSTRIDE = GRID * TPB;

    // ---- Phase 0a: pull + pack edges (ATS reads of static host arrays) ----
    for (int e = gtid; e < p.nedges; e += GSTRIDE) {
        uint32_t v = hostE[e];
        int src  = (int)(v & 0xFFFu);
        int widx = (int)(v >> 12);
        g_packed[e] = make_float2(weights[widx], __int_as_float(src * BATCH));
    }
    for (int r = gtid; r <= N_DST; r += GSTRIDE)
        g_rowptr[r] = hostR[r];

    // ---- Phase 0b: embedding into fp16 slab (half2 per thread-iter) -------
    for (int i = gtid; i < N_SRC0 * (BATCH / 2); i += GSTRIDE) {
        int node = i >> 8;               // BATCH/2 = 256 half2 per node
        int b2   = (i & 255) * 2;        // batch column pair
        float v0, v1;
        if (node < N_IN) {
            int t = node >> 5, d = node & 31;
            float pv = pos[node];
            v0 = tok[ids[(b2    ) * T_LEN + t] * D_MODEL + d] + pv;
            v1 = tok[ids[(b2 + 1) * T_LEN + t] * D_MODEL + d] + pv;
        } else {
            v0 = v1 = 1.0f;
        }
        __half2 h = __floats2half2_rn(v0, v1);
        *(__half2*)(g_vals + node * BATCH + b2) = h;
    }

    grid_barrier(0);

    // ---- Sparse layers ----------------------------------------------------
    for (int l = 0; l < NLAY; l++) {
        int size    = p.size[l];
        int rb      = p.row_base[l];
        int nb      = p.node_base[l];
        int is_last = (l == NLAY - 1);
        int nitems  = size * 4;              // 4 col-groups of 128 columns

        for (int it = blockIdx.x; it < nitems; it += GRID) {
            int dst = it >> 2;
            int c   = (it & 3) * 128 + lane * 4;   // 4 consecutive batch cols

            float4 a = make_float4(0.f, 0.f, 0.f, 0.f);
            {
                int e0  = g_rowptr[rb + dst];
                int len = g_rowptr[rb + dst + 1] - e0;
                int es  = e0 + (len * seg) / NSEG;
                int ee  = e0 + (len * (seg + 1)) / NSEG;
                if (es < ee) {
                    float2 pr = g_packed[es];
                    for (int e = es + 1; e < ee; e++) {
                        float2 pn = g_packed[e];   // prefetch next record
                        uint2 raw = *(const uint2*)(g_vals + (__float_as_int(pr.y) + c));
                        float2 f01 = __half22float2(*reinterpret_cast<__half2*>(&raw.x));
                        float2 f23 = __half22float2(*reinterpret_cast<__half2*>(&raw.y));
                        a.x = fmaf(pr.x, f01.x, a.x);
                        a.y = fmaf(pr.x, f01.y, a.y);
                        a.z = fmaf(pr.x, f23.x, a.z);
                        a.w = fmaf(pr.x, f23.y, a.w);
                        pr = pn;
                    }
                    uint2 raw = *(const uint2*)(g_vals + (__float_as_int(pr.y) + c));
                    float2 f01 = __half22float2(*reinterpret_cast<__half2*>(&raw.x));
                    float2 f23 = __half22float2(*reinterpret_cast<__half2*>(&raw.y));
                    a.x = fmaf(pr.x, f01.x, a.x);
                    a.y = fmaf(pr.x, f01.y, a.y);
                    a.z = fmaf(pr.x, f23.x, a.z);
                    a.w = fmaf(pr.x, f23.y, a.w);
                }
            }
            red[seg][lane] = a;
            __syncthreads();

            if (seg == 0) {
                float4 s = red[0][lane];
                #pragma unroll
                for (int k = 1; k < NSEG; k++) {
                    float4 t = red[k][lane];
                    s.x += t.x; s.y += t.y; s.z += t.z; s.w += t.w;
                }
                if (is_last) {
                    out[(c    ) * VOCAB + dst] = s.x;  // logits [B, V], fp32
                    out[(c + 1) * VOCAB + dst] = s.y;
                    out[(c + 2) * VOCAB + dst] = s.z;
                    out[(c + 3) * VOCAB + dst] = s.w;
                } else {
                    __half2 h01 = __floats2half2_rn(tanhf(s.x), tanhf(s.y));
                    __half2 h23 = __floats2half2_rn(tanhf(s.z), tanhf(s.w));
                    uint2 raw;
                    raw.x = *reinterpret_cast<uint32_t*>(&h01);
                    raw.y = *reinterpret_cast<uint32_t*>(&h23);
                    *(uint2*)(g_vals + ((nb + dst) * BATCH + c)) = raw;
                }
            }
            __syncthreads();   // red reuse protection for next item
        }

        if (!is_last) grid_barrier(l + 1);
    }
}

// ===================== Launch ===============================================
extern "C" void kernel_launch(void* const* d_in, const int* in_sizes, int n_in,
                              void* d_out, int out_size) {
    const int*   ids = (const int*)  d_in[0];
    const float* tok = (const float*)d_in[1];
    const float* pos = (const float*)d_in[2];
    const float* wts = (const float*)d_in[3];
    float*       out = (float*)d_out;

    // Host-side, deterministic, rebuilt identically on every call.
    build_graph_host();

    rwnn_kernel<<<GRID, TPB>>>(h_params, h_emeta, h_rowptr,
                               ids, tok, pos, wts, out);
}

// round 10
// speedup vs baseline: 1.0565x; 1.0565x over previous
#include <cuda_runtime.h>
#include <cuda_fp16.h>
#include <cstdint>
#include <cstring>
#include <algorithm>

// ===================== Problem constants (static graph) =====================
#define VOCAB    512
#define T_LEN    64
#define D_MODEL  32
#define N_NODES  4000
#define N_LAYERS 5
#define N_BIAS   2
#define BATCH    512
#define N_IN     (T_LEN * D_MODEL)          // 2048
#define N_SRC0   (N_IN + N_BIAS)            // 2050 : first dst node id
#define N_DST    (N_NODES - N_SRC0)         // 1950 : hidden + vocab dst nodes
#define MAX_EDGES 262144                    // expected ~166.8k

#define NSEG 8                               // edge segments per dst row
#define TPB  (32 * NSEG)                     // 256 threads, one (dst, colgrp)/block

// ===================== Device globals (no allocation allowed) ===============
__device__ float2 g_packed[MAX_EDGES];                    // {weight, __int_as_float(src*BATCH)}
__device__ int    g_rowptr[N_DST + 2];                    // CSR over local dst index
__device__ __align__(128) __half g_vals[N_NODES * BATCH]; // fp16 activation slab (4.1 MB)

// ===================== Host-side: numpy-exact MT19937 =======================
struct MT19937 {
    uint32_t mt[624];
    int idx;
    void seed(uint32_t s) {
        mt[0] = s;
        for (int i = 1; i < 624; i++)
            mt[i] = 1812433253u * (mt[i - 1] ^ (mt[i - 1] >> 30)) + (uint32_t)i;
        idx = 624;
    }
    inline uint32_t next() {
        if (idx >= 624) {
            for (int i = 0; i < 624; i++) {
                uint32_t y = (mt[i] & 0x80000000u) | (mt[(i + 1) % 624] & 0x7fffffffu);
                mt[i] = mt[(i + 397) % 624] ^ (y >> 1);
                if (y & 1u) mt[i] ^= 0x9908b0dfu;
            }
            idx = 0;
        }
        uint32_t y = mt[idx++];
        y ^= y >> 11;
        y ^= (y << 7)  & 0x9d2c5680u;
        y ^= (y << 15) & 0xefc60000u;
        y ^= y >> 18;
        return y;
    }
    inline double rdouble() {  // numpy legacy rk_double
        uint32_t a = next() >> 5, b = next() >> 6;
        return ((double)a * 67108864.0 + (double)b) / 9007199254740992.0;
    }
    inline uint64_t next64() {  // numpy mt19937_next64: hi then lo
        uint64_t hi = next();
        uint64_t lo = next();
        return (hi << 32) | lo;
    }
};

// ===================== Host graph build (exact numpy replica) ===============
struct LayerInfo { int node_base; int row_base; int size; };

static uint32_t  h_emeta[MAX_EDGES];   // (widx << 12) | src  : GPU reads via ATS
static int       h_rowptr[N_DST + 2];
static LayerInfo h_layers[N_LAYERS + 1];
static int       h_nedges;

static void build_graph_host() {
    MT19937 mt;
    mt.seed(0u);

    int sizes[N_LAYERS + 1];
    {
        int nh = N_NODES - N_SRC0 - VOCAB;  // 1438
        for (int i = 0; i < N_LAYERS; i++)
            sizes[i] = nh / N_LAYERS + (i < nh % N_LAYERS ? 1 : 0);
        sizes[N_LAYERS] = VOCAB;
    }

    static int esrc[MAX_EDGES];
    static int edst[MAX_EDGES];

    int start = N_SRC0;
    int row_base = 0;
    int eidx = 0;

    for (int l = 0; l < N_LAYERS + 1; l++) {
        int size = sizes[l];
        int lbase = eidx;
        int colcnt[VOCAB];
        for (int v = 0; v < size; v++) colcnt[v] = 0;

        for (int u = 0; u < start; u++) {
            for (int v = 0; v < size; v++) {
                double x = mt.rdouble();
                if (x < 0.03) {
                    esrc[eidx] = u;
                    edst[eidx] = v;
                    colcnt[v]++;
                    eidx++;
                }
            }
        }

        // empty-column fix (probability ~1e-24; exact replica anyway)
        int emptyCols[VOCAB], nEmpty = 0;
        for (int v = 0; v < size; v++) if (colcnt[v] == 0) emptyCols[nEmpty++] = v;
        if (nEmpty) {
            uint64_t rng = (uint64_t)(start - 1);
            uint64_t mask = rng;
            mask |= mask >> 1; mask |= mask >> 2; mask |= mask >> 4;
            mask |= mask >> 8; mask |= mask >> 16; mask |= mask >> 32;
            for (int k = 0; k < nEmpty; k++) {
                uint64_t val;
                do { val = mt.next64() & mask; } while (val > rng);
                esrc[eidx] = (int)val;
                edst[eidx] = emptyCols[k];
                colcnt[emptyCols[k]]++;
                eidx++;
            }
            struct P { int s, d; };
            static P tmp[MAX_EDGES];
            int n = eidx - lbase;
            for (int i = 0; i < n; i++) tmp[i] = {esrc[lbase + i], edst[lbase + i]};
            std::sort(tmp, tmp + n, [](const P& a, const P& b) {
                return a.s != b.s ? a.s < b.s : a.d < b.d;
            });
            for (int i = 0; i < n; i++) { esrc[lbase + i] = tmp[i].s; edst[lbase + i] = tmp[i].d; }
        }

        // dst-sorted CSR; weight index = src-major position (== e)
        int colstart[VOCAB + 1];
        colstart[0] = lbase;
        for (int v = 0; v < size; v++) colstart[v + 1] = colstart[v] + colcnt[v];
        for (int v = 0; v < size; v++) h_rowptr[row_base + v] = colstart[v];
        int fill[VOCAB];
        for (int v = 0; v < size; v++) fill[v] = colstart[v];
        for (int e = lbase; e < eidx; e++) {
            int v = edst[e];
            h_emeta[fill[v]] = ((uint32_t)e << 12) | (uint32_t)esrc[e];
            fill[v]++;
        }

        h_layers[l].node_base = start;
        h_layers[l].row_base  = row_base;
        h_layers[l].size      = size;
        row_base += size;
        start    += size;
    }
    h_rowptr[N_DST] = eidx;
    h_nedges = eidx;
}

// ===================== Kernels ==============================================

// Pull compressed graph meta from HOST memory (Grace ATS / NVLink-C2C),
// gather runtime weights, and write packed edge records {w, src_offset}.
__global__ void pull_pack_kernel(const uint32_t* __restrict__ hostE,
                                 const int*      __restrict__ hostR,
                                 const float*    __restrict__ weights,
                                 int nE) {
    int i = blockIdx.x * blockDim.x + threadIdx.x;
    int stride = gridDim.x * blockDim.x;
    for (int e = i; e < nE; e += stride) {
        uint32_t v = hostE[e];
        int src  = (int)(v & 0xFFFu);
        int widx = (int)(v >> 12);
        g_packed[e] = make_float2(weights[widx], __int_as_float(src * BATCH));
    }
    for (int r = i; r <= N_DST; r += stride)
        g_rowptr[r] = hostR[r];
}

// vals[node][b] for input + bias nodes (fp16)
__global__ void embed_kernel(const int* __restrict__ ids,
                             const float* __restrict__ tok,
                             const float* __restrict__ pos) {
    int b    = blockIdx.x * 32 + (threadIdx.x & 31);
    int node = blockIdx.y * 8 + (threadIdx.x >> 5);
    if (node >= N_SRC0) return;
    float v;
    if (node < N_IN) {
        int t = node >> 5;          // node = t*D + d, D = 32
        v = tok[ids[b * T_LEN + t] * D_MODEL + (node & 31)] + pos[node];
    } else {
        v = 1.0f;
    }
    g_vals[node * BATCH + b] = __float2half_rn(v);
}

// fma of 8 fp16 values (one uint4 = 4 half2) into two float4 accumulators.
__device__ __forceinline__ void fma8(float4& A, float4& B, float w, uint4 r) {
    float2 f0 = __half22float2(*reinterpret_cast<__half2*>(&r.x));
    float2 f1 = __half22float2(*reinterpret_cast<__half2*>(&r.y));
    float2 f2 = __half22float2(*reinterpret_cast<__half2*>(&r.z));
    float2 f3 = __half22float2(*reinterpret_cast<__half2*>(&r.w));
    A.x = fmaf(w, f0.x, A.x); A.y = fmaf(w, f0.y, A.y);
    A.z = fmaf(w, f1.x, A.z); A.w = fmaf(w, f1.y, A.w);
    B.x = fmaf(w, f2.x, B.x); B.y = fmaf(w, f2.y, B.y);
    B.z = fmaf(w, f3.x, B.z); B.w = fmaf(w, f3.y, B.w);
}

// Block = 32 lanes x NSEG segments, one (dst row, 256-col group) per block.
// Lane owns 8 consecutive columns: per edge -> 1 broadcast LDG.64 record +
// 1 coalesced LDG.128 of fp16 values. Segment loop unrolled x4: 4 records +
// 4 value loads in flight (MLP=4) to break the L2 dependent chain.
__global__ void __launch_bounds__(TPB, 4)
layer_kernel(float* __restrict__ out,
             int node_base, int row_base, int size, int is_last) {
    __shared__ float4 redA[NSEG][32];
    __shared__ float4 redB[NSEG][32];

    int tid  = threadIdx.x;
    int lane = tid & 31;
    int seg  = tid >> 5;
    int dst  = blockIdx.y;
    int c    = blockIdx.x * 256 + lane * 8;     // 8 consecutive batch columns

    float4 A = make_float4(0.f, 0.f, 0.f, 0.f);
    float4 B = make_float4(0.f, 0.f, 0.f, 0.f);
    {
        int e0  = g_rowptr[row_base + dst];
        int len = g_rowptr[row_base + dst + 1] - e0;
        int es  = e0 + (len * seg) / NSEG;
        int ee  = e0 + (len * (seg + 1)) / NSEG;
        int e   = es;
        for (; e + 4 <= ee; e += 4) {
            float2 p0 = g_packed[e    ];
            float2 p1 = g_packed[e + 1];
            float2 p2 = g_packed[e + 2];
            float2 p3 = g_packed[e + 3];
            uint4 r0 = *(const uint4*)(g_vals + (__float_as_int(p0.y) + c));
            uint4 r1 = *(const uint4*)(g_vals + (__float_as_int(p1.y) + c));
            uint4 r2 = *(const uint4*)(g_vals + (__float_as_int(p2.y) + c));
            uint4 r3 = *(const uint4*)(g_vals + (__float_as_int(p3.y) + c));
            fma8(A, B, p0.x, r0);
            fma8(A, B, p1.x, r1);
            fma8(A, B, p2.x, r2);
            fma8(A, B, p3.x, r3);
        }
        for (; e < ee; e++) {
            float2 p = g_packed[e];
            uint4 r = *(const uint4*)(g_vals + (__float_as_int(p.y) + c));
            fma8(A, B, p.x, r);
        }
    }
    redA[seg][lane] = A;
    redB[seg][lane] = B;
    __syncthreads();

    if (seg == 0) {
        float4 sA = redA[0][lane];
        float4 sB = redB[0][lane];
        #pragma unroll
        for (int k = 1; k < NSEG; k++) {
            float4 tA = redA[k][lane];
            float4 tB = redB[k][lane];
            sA.x += tA.x; sA.y += tA.y; sA.z += tA.z; sA.w += tA.w;
            sB.x += tB.x; sB.y += tB.y; sB.z += tB.z; sB.w += tB.w;
        }
        if (is_last) {
            out[(c    ) * VOCAB + dst] = sA.x;  // logits [B, V] row-major, fp32
            out[(c + 1) * VOCAB + dst] = sA.y;
            out[(c + 2) * VOCAB + dst] = sA.z;
            out[(c + 3) * VOCAB + dst] = sA.w;
            out[(c + 4) * VOCAB + dst] = sB.x;
            out[(c + 5) * VOCAB + dst] = sB.y;
            out[(c + 6) * VOCAB + dst] = sB.z;
            out[(c + 7) * VOCAB + dst] = sB.w;
        } else {
            __half2 h0 = __floats2half2_rn(tanhf(sA.x), tanhf(sA.y));
            __half2 h1 = __floats2half2_rn(tanhf(sA.z), tanhf(sA.w));
            __half2 h2 = __floats2half2_rn(tanhf(sB.x), tanhf(sB.y));
            __half2 h3 = __floats2half2_rn(tanhf(sB.z), tanhf(sB.w));
            uint4 raw;
            raw.x = *reinterpret_cast<uint32_t*>(&h0);
            raw.y = *reinterpret_cast<uint32_t*>(&h1);
            raw.z = *reinterpret_cast<uint32_t*>(&h2);
            raw.w = *reinterpret_cast<uint32_t*>(&h3);
            *(uint4*)(g_vals + ((node_base + dst) * BATCH + c)) = raw;
        }
    }
}

// ===================== Launch ===============================================
extern "C" void kernel_launch(void* const* d_in, const int* in_sizes, int n_in,
                              void* d_out, int out_size) {
    const int*   ids = (const int*)  d_in[0];
    const float* tok = (const float*)d_in[1];
    const float* pos = (const float*)d_in[2];
    const float* wts = (const float*)d_in[3];
    float*       out = (float*)d_out;

    // Host-side, deterministic, rebuilt identically on every call.
    build_graph_host();

    pull_pack_kernel<<<512, 256>>>(h_emeta, h_rowptr, wts, h_nedges);

    embed_kernel<<<dim3(BATCH / 32, (N_SRC0 + 7) / 8), 256>>>(ids, tok, pos);

    for (int l = 0; l < N_LAYERS + 1; l++) {
        int sz = h_layers[l].size;
        layer_kernel<<<dim3(BATCH / 256, sz), TPB>>>(
            out, h_layers[l].node_base, h_layers[l].row_base, sz,
            l == N_LAYERS ? 1 : 0);
    }
}

// round 12
// speedup vs baseline: 1.6075x; 1.5215x over previous
#include <cuda_runtime.h>
#include <cuda_fp16.h>
#include <cstdint>
#include <cstring>
#include <algorithm>

// ===================== Problem constants (static graph) =====================
#define VOCAB    512
#define T_LEN    64
#define D_MODEL  32
#define N_NODES  4000
#define N_LAYERS 5
#define N_BIAS   2
#define BATCH    512
#define N_IN     (T_LEN * D_MODEL)          // 2048
#define N_SRC0   (N_IN + N_BIAS)            // 2050 : first dst node id
#define N_DST    (N_NODES - N_SRC0)         // 1950 : hidden + vocab dst nodes
#define MAX_EDGES 262144                    // expected ~166.8k

#define NSEG 8                               // edge segments per item
#define TPB  (32 * NSEG)                     // 256 threads, one (dst, colgrp)/block
#define CHUNK 512                            // records staged to smem per pass

// ===================== Device globals (no allocation allowed) ===============
__device__ float2 g_packed[MAX_EDGES];                    // {weight, __int_as_float(src*BATCH)}
__device__ int    g_rowptr[N_DST + 2];                    // CSR over local dst index
__device__ __align__(128) __half g_vals[N_NODES * BATCH]; // fp16 activation slab (4.1 MB)

// ===================== Host-side: numpy-exact MT19937 =======================
struct MT19937 {
    uint32_t mt[624];
    int idx;
    void seed(uint32_t s) {
        mt[0] = s;
        for (int i = 1; i < 624; i++)
            mt[i] = 1812433253u * (mt[i - 1] ^ (mt[i - 1] >> 30)) + (uint32_t)i;
        idx = 624;
    }
    inline uint32_t next() {
        if (idx >= 624) {
            for (int i = 0; i < 624; i++) {
                uint32_t y = (mt[i] & 0x80000000u) | (mt[(i + 1) % 624] & 0x7fffffffu);
                mt[i] = mt[(i + 397) % 624] ^ (y >> 1);
                if (y & 1u) mt[i] ^= 0x9908b0dfu;
            }
            idx = 0;
        }
        uint32_t y = mt[idx++];
        y ^= y >> 11;
        y ^= (y << 7)  & 0x9d2c5680u;
        y ^= (y << 15) & 0xefc60000u;
        y ^= y >> 18;
        return y;
    }
    inline double rdouble() {  // numpy legacy rk_double
        uint32_t a = next() >> 5, b = next() >> 6;
        return ((double)a * 67108864.0 + (double)b) / 9007199254740992.0;
    }
    inline uint64_t next64() {  // numpy mt19937_next64: hi then lo
        uint64_t hi = next();
        uint64_t lo = next();
        return (hi << 32) | lo;
    }
};

// ===================== Host graph build (exact numpy replica) ===============
struct LayerInfo { int node_base; int row_base; int size; };

static uint32_t  h_emeta[MAX_EDGES];   // (widx << 12) | src  : GPU reads via ATS
static int       h_rowptr[N_DST + 2];
static LayerInfo h_layers[N_LAYERS + 1];
static int       h_nedges;

static void build_graph_host() {
    MT19937 mt;
    mt.seed(0u);

    int sizes[N_LAYERS + 1];
    {
        int nh = N_NODES - N_SRC0 - VOCAB;  // 1438
        for (int i = 0; i < N_LAYERS; i++)
            sizes[i] = nh / N_LAYERS + (i < nh % N_LAYERS ? 1 : 0);
        sizes[N_LAYERS] = VOCAB;
    }

    static int esrc[MAX_EDGES];
    static int edst[MAX_EDGES];

    int start = N_SRC0;
    int row_base = 0;
    int eidx = 0;

    for (int l = 0; l < N_LAYERS + 1; l++) {
        int size = sizes[l];
        int lbase = eidx;
        int colcnt[VOCAB];
        for (int v = 0; v < size; v++) colcnt[v] = 0;

        for (int u = 0; u < start; u++) {
            for (int v = 0; v < size; v++) {
                double x = mt.rdouble();
                if (x < 0.03) {
                    esrc[eidx] = u;
                    edst[eidx] = v;
                    colcnt[v]++;
                    eidx++;
                }
            }
        }

        // empty-column fix (probability ~1e-24; exact replica anyway)
        int emptyCols[VOCAB], nEmpty = 0;
        for (int v = 0; v < size; v++) if (colcnt[v] == 0) emptyCols[nEmpty++] = v;
        if (nEmpty) {
            uint64_t rng = (uint64_t)(start - 1);
            uint64_t mask = rng;
            mask |= mask >> 1; mask |= mask >> 2; mask |= mask >> 4;
            mask |= mask >> 8; mask |= mask >> 16; mask |= mask >> 32;
            for (int k = 0; k < nEmpty; k++) {
                uint64_t val;
                do { val = mt.next64() & mask; } while (val > rng);
                esrc[eidx] = (int)val;
                edst[eidx] = emptyCols[k];
                colcnt[emptyCols[k]]++;
                eidx++;
            }
            struct P { int s, d; };
            static P tmp[MAX_EDGES];
            int n = eidx - lbase;
            for (int i = 0; i < n; i++) tmp[i] = {esrc[lbase + i], edst[lbase + i]};
            std::sort(tmp, tmp + n, [](const P& a, const P& b) {
                return a.s != b.s ? a.s < b.s : a.d < b.d;
            });
            for (int i = 0; i < n; i++) { esrc[lbase + i] = tmp[i].s; edst[lbase + i] = tmp[i].d; }
        }

        // dst-sorted CSR; weight index = src-major position (== e)
        int colstart[VOCAB + 1];
        colstart[0] = lbase;
        for (int v = 0; v < size; v++) colstart[v + 1] = colstart[v] + colcnt[v];
        for (int v = 0; v < size; v++) h_rowptr[row_base + v] = colstart[v];
        int fill[VOCAB];
        for (int v = 0; v < size; v++) fill[v] = colstart[v];
        for (int e = lbase; e < eidx; e++) {
            int v = edst[e];
            h_emeta[fill[v]] = ((uint32_t)e << 12) | (uint32_t)esrc[e];
            fill[v]++;
        }

        h_layers[l].node_base = start;
        h_layers[l].row_base  = row_base;
        h_layers[l].size      = size;
        row_base += size;
        start    += size;
    }
    h_rowptr[N_DST] = eidx;
    h_nedges = eidx;
}

// ===================== Kernels ==============================================

// Pull compressed graph meta from HOST memory (Grace ATS / NVLink-C2C),
// gather runtime weights, and write packed edge records {w, src_offset}.
__global__ void pull_pack_kernel(const uint32_t* __restrict__ hostE,
                                 const int*      __restrict__ hostR,
                                 const float*    __restrict__ weights,
                                 int nE) {
    int i = blockIdx.x * blockDim.x + threadIdx.x;
    int stride = gridDim.x * blockDim.x;
    for (int e = i; e < nE; e += stride) {
        uint32_t v = hostE[e];
        int src  = (int)(v & 0xFFFu);
        int widx = (int)(v >> 12);
        g_packed[e] = make_float2(weights[widx], __int_as_float(src * BATCH));
    }
    for (int r = i; r <= N_DST; r += stride)
        g_rowptr[r] = hostR[r];
}

// vals[node][b] for input + bias nodes (fp16)
__global__ void embed_kernel(const int* __restrict__ ids,
                             const float* __restrict__ tok,
                             const float* __restrict__ pos) {
    int b    = blockIdx.x * 32 + (threadIdx.x & 31);
    int node = blockIdx.y * 8 + (threadIdx.x >> 5);
    if (node >= N_SRC0) return;
    float v;
    if (node < N_IN) {
        int t = node >> 5;          // node = t*D + d, D = 32
        v = tok[ids[b * T_LEN + t] * D_MODEL + (node & 31)] + pos[node];
    } else {
        v = 1.0f;
    }
    g_vals[node * BATCH + b] = __float2half_rn(v);
}

// fma of 8 fp16 values (one uint4 = 4 half2) into two float4 accumulators.
__device__ __forceinline__ void fma8(float4& A, float4& B, float w, uint4 r) {
    float2 f0 = __half22float2(*reinterpret_cast<__half2*>(&r.x));
    float2 f1 = __half22float2(*reinterpret_cast<__half2*>(&r.y));
    float2 f2 = __half22float2(*reinterpret_cast<__half2*>(&r.z));
    float2 f3 = __half22float2(*reinterpret_cast<__half2*>(&r.w));
    A.x = fmaf(w, f0.x, A.x); A.y = fmaf(w, f0.y, A.y);
    A.z = fmaf(w, f1.x, A.z); A.w = fmaf(w, f1.y, A.w);
    B.x = fmaf(w, f2.x, B.x); B.y = fmaf(w, f2.y, B.y);
    B.z = fmaf(w, f3.x, B.z); B.w = fmaf(w, f3.y, B.w);
}

// Block = 32 lanes x NSEG segments, one (dst row, 256-col group) per block.
// KEY CHANGE vs the 9us plateau: the block first stages its row's edge
// records into SMEM (coalesced burst, 2 records/thread), then the gather
// loop reads records via LDS (fixed ~29-cyc latency, no global scoreboard
// chain) so value LDGs pipeline back-to-back instead of serializing behind
// in-flight record loads.
__global__ void __launch_bounds__(TPB, 4)
layer_kernel(float* __restrict__ out,
             int node_base, int row_base, int size, int is_last) {
    __shared__ float2 srec[CHUNK];
    __shared__ float4 redA[NSEG][32];
    __shared__ float4 redB[NSEG][32];

    int tid  = threadIdx.x;
    int lane = tid & 31;
    int seg  = tid >> 5;
    int dst  = blockIdx.y;
    int c    = blockIdx.x * 256 + lane * 8;     // 8 consecutive batch columns

    int e0 = g_rowptr[row_base + dst];
    int e1 = g_rowptr[row_base + dst + 1];

    float4 A = make_float4(0.f, 0.f, 0.f, 0.f);
    float4 B = make_float4(0.f, 0.f, 0.f, 0.f);

    for (int base = e0; base < e1; base += CHUNK) {
        int L = min(CHUNK, e1 - base);
        if (tid < L)       srec[tid]       = g_packed[base + tid];
        if (tid + TPB < L) srec[tid + TPB] = g_packed[base + tid + TPB];
        __syncthreads();

        int s0 = (L * seg) >> 3;        // this segment's slice of the chunk
        int s1 = (L * (seg + 1)) >> 3;
        int i  = s0;
        for (; i + 4 <= s1; i += 4) {
            float2 p0 = srec[i    ];    // LDS broadcast: fixed latency
            float2 p1 = srec[i + 1];
            float2 p2 = srec[i + 2];
            float2 p3 = srec[i + 3];
            uint4 r0 = *(const uint4*)(g_vals + (__float_as_int(p0.y) + c));
            uint4 r1 = *(const uint4*)(g_vals + (__float_as_int(p1.y) + c));
            uint4 r2 = *(const uint4*)(g_vals + (__float_as_int(p2.y) + c));
            uint4 r3 = *(const uint4*)(g_vals + (__float_as_int(p3.y) + c));
            fma8(A, B, p0.x, r0);
            fma8(A, B, p1.x, r1);
            fma8(A, B, p2.x, r2);
            fma8(A, B, p3.x, r3);
        }
        for (; i < s1; i++) {
            float2 p = srec[i];
            uint4 r = *(const uint4*)(g_vals + (__float_as_int(p.y) + c));
            fma8(A, B, p.x, r);
        }
        __syncthreads();                // srec reuse protection
    }

    redA[seg][lane] = A;
    redB[seg][lane] = B;
    __syncthreads();

    if (seg == 0) {
        float4 sA = redA[0][lane];
        float4 sB = redB[0][lane];
        #pragma unroll
        for (int k = 1; k < NSEG; k++) {
            float4 tA = redA[k][lane];
            float4 tB = redB[k][lane];
            sA.x += tA.x; sA.y += tA.y; sA.z += tA.z; sA.w += tA.w;
            sB.x += tB.x; sB.y += tB.y; sB.z += tB.z; sB.w += tB.w;
        }
        if (is_last) {
            out[(c    ) * VOCAB + dst] = sA.x;  // logits [B, V] row-major, fp32
            out[(c + 1) * VOCAB + dst] = sA.y;
            out[(c + 2) * VOCAB + dst] = sA.z;
            out[(c + 3) * VOCAB + dst] = sA.w;
            out[(c + 4) * VOCAB + dst] = sB.x;
            out[(c + 5) * VOCAB + dst] = sB.y;
            out[(c + 6) * VOCAB + dst] = sB.z;
            out[(c + 7) * VOCAB + dst] = sB.w;
        } else {
            __half2 h0 = __floats2half2_rn(tanhf(sA.x), tanhf(sA.y));
            __half2 h1 = __floats2half2_rn(tanhf(sA.z), tanhf(sA.w));
            __half2 h2 = __floats2half2_rn(tanhf(sB.x), tanhf(sB.y));
            __half2 h3 = __floats2half2_rn(tanhf(sB.z), tanhf(sB.w));
            uint4 raw;
            raw.x = *reinterpret_cast<uint32_t*>(&h0);
            raw.y = *reinterpret_cast<uint32_t*>(&h1);
            raw.z = *reinterpret_cast<uint32_t*>(&h2);
            raw.w = *reinterpret_cast<uint32_t*>(&h3);
            *(uint4*)(g_vals + ((node_base + dst) * BATCH + c)) = raw;
        }
    }
}

// ===================== Launch ===============================================
extern "C" void kernel_launch(void* const* d_in, const int* in_sizes, int n_in,
                              void* d_out, int out_size) {
    const int*   ids = (const int*)  d_in[0];
    const float* tok = (const float*)d_in[1];
    const float* pos = (const float*)d_in[2];
    const float* wts = (const float*)d_in[3];
    float*       out = (float*)d_out;

    // Host-side, deterministic, rebuilt identically on every call.
    build_graph_host();

    pull_pack_kernel<<<512, 256>>>(h_emeta, h_rowptr, wts, h_nedges);

    embed_kernel<<<dim3(BATCH / 32, (N_SRC0 + 7) / 8), 256>>>(ids, tok, pos);

    for (int l = 0; l < N_LAYERS + 1; l++) {
        int sz = h_layers[l].size;
        layer_kernel<<<dim3(BATCH / 256, sz), TPB>>>(
            out, h_layers[l].node_base, h_layers[l].row_base, sz,
            l == N_LAYERS ? 1 : 0);
    }
}